// round 15
// baseline (speedup 1.0000x reference)
#include <cuda_runtime.h>
#include <cuda_fp16.h>
#include <cstdint>
#include <math.h>

#define T 2048        // B*S tokens
#define D 1024
#define Hh 2048
#define E 8
#define TWOH 4096
#define NSLOT (T * 2)

// ---- scratch ----
__device__ int    g_cnt[E];
__device__ int    g_list[E][T];
__device__ float  g_wt[NSLOT];
__device__ __half g_xh[(size_t)T * D];            // fp16 x (4 MB)
__device__ __half g_hiddenh[(size_t)NSLOT * Hh];  // fp16 hidden (16 MB)
__device__ float  g_aux;

// ======================= helpers =======================
__device__ __forceinline__ uint32_t smem_u32(const void* p) {
    uint32_t a;
    asm("{ .reg .u64 t; cvta.to.shared.u64 t, %1; cvt.u32.u64 %0, t; }" : "=r"(a) : "l"(p));
    return a;
}
__device__ __forceinline__ uint32_t h2u(__half2 h) { return *(uint32_t*)&h; }

#define CP_ASYNC16(dst, src) \
    asm volatile("cp.async.cg.shared.global [%0], [%1], 16;" :: "r"(dst), "l"(src))
#define CP_COMMIT() asm volatile("cp.async.commit_group;")
#define CP_WAIT0()  asm volatile("cp.async.wait_group 0;" ::: "memory")

__device__ __forceinline__ void ldsm4(uint32_t* r, uint32_t addr) {
    asm volatile("ldmatrix.sync.aligned.m8n8.x4.shared.b16 {%0,%1,%2,%3},[%4];"
        : "=r"(r[0]), "=r"(r[1]), "=r"(r[2]), "=r"(r[3]) : "r"(addr));
}
__device__ __forceinline__ void ldsm4t(uint32_t* r, uint32_t addr) {
    asm volatile("ldmatrix.sync.aligned.m8n8.x4.trans.shared.b16 {%0,%1,%2,%3},[%4];"
        : "=r"(r[0]), "=r"(r[1]), "=r"(r[2]), "=r"(r[3]) : "r"(addr));
}
__device__ __forceinline__ void mma16(float* c, const uint32_t* a, uint32_t b0, uint32_t b1) {
    asm volatile(
        "mma.sync.aligned.m16n8k16.row.col.f32.f16.f16.f32 "
        "{%0,%1,%2,%3},{%4,%5,%6,%7},{%8,%9},{%0,%1,%2,%3};"
        : "+f"(c[0]), "+f"(c[1]), "+f"(c[2]), "+f"(c[3])
        : "r"(a[0]), "r"(a[1]), "r"(a[2]), "r"(a[3]), "r"(b0), "r"(b1));
}

// ======================= small kernels =======================
// tiny init: expert counters + aux
__global__ void zero_kernel() {
    int i = threadIdx.x;
    if (i < E) g_cnt[i] = 0;
    if (i == 0) g_aux = 0.0f;
}

// router + x->fp16 conversion + out-row zeroing, fused (one warp per token)
__global__ void router_kernel(const float* __restrict__ x,
                              const float* __restrict__ rw,
                              const float* __restrict__ rb,
                              float* __restrict__ out) {
    int warp = threadIdx.x >> 5;
    int lane = threadIdx.x & 31;
    int t = blockIdx.x * (blockDim.x >> 5) + warp;
    if (t >= T) return;

    // zero this token's output row (atomic accumulation target)
    {
        float4* orow = (float4*)(out + (size_t)t * D);
#pragma unroll
        for (int j = 0; j < 8; j++)
            orow[lane + j * 32] = make_float4(0.f, 0.f, 0.f, 0.f);
    }

    const float2* xr = (const float2*)(x + (size_t)t * D);
    uint32_t* xo = (uint32_t*)(g_xh + (size_t)t * D);
    float acc[E];
#pragma unroll
    for (int e = 0; e < E; e++) acc[e] = 0.0f;
#pragma unroll 4
    for (int p = lane; p < D / 2; p += 32) {
        float2 v = xr[p];
        xo[p] = h2u(__floats2half2_rn(v.x, v.y));
#pragma unroll
        for (int e = 0; e < E; e++)
            acc[e] += v.x * rw[e * D + 2 * p] + v.y * rw[e * D + 2 * p + 1];
    }
#pragma unroll
    for (int e = 0; e < E; e++) {
#pragma unroll
        for (int off = 16; off; off >>= 1)
            acc[e] += __shfl_xor_sync(0xffffffffu, acc[e], off);
    }
    if (lane == 0) {
        float score[E];
        float auxl = 0.0f;
#pragma unroll
        for (int e = 0; e < E; e++) {
            float lg = acc[e] + rb[e];
            auxl += lg * lg;
            score[e] = 1.0f / (1.0f + expf(-lg));
        }
        int e0 = 0;
#pragma unroll
        for (int e = 1; e < E; e++) if (score[e] > score[e0]) e0 = e;
        int e1 = -1;
#pragma unroll
        for (int e = 0; e < E; e++) {
            if (e == e0) continue;
            if (e1 < 0 || score[e] > score[e1]) e1 = e;
        }
        float s0 = score[e0], s1 = score[e1];
        float inv = 1.0f / (s0 + s1 + 1e-6f);
        g_wt[2 * t]     = s0 * inv;
        g_wt[2 * t + 1] = s1 * inv;
        int p0 = atomicAdd(&g_cnt[e0], 1); g_list[e0][p0] = 2 * t;
        int p1 = atomicAdd(&g_cnt[e1], 1); g_list[e1][p1] = 2 * t + 1;
        atomicAdd(&g_aux, auxl);
    }
}

// ======================= GEMM1 layout (unchanged from R9) =======================
// slot[128]@0, tok[128]@512
// A: [m:128][k:64] fp16, row stride 144B. stage = 18432B x2
// B: [k:64][n:128+8pad] fp16, row stride 272B. stage = 17408B x2
#define A_OFF 1024
#define A_STG 18432
#define B_OFF (1024 + 2 * 18432)
#define B_STG 17408
#define G1_SMEM (B_OFF + 2 * 17408)

// ======================= GEMM2 layout (M=64) =======================
#define A2_STG 9216                       // 64 rows * 144B
#define B2_OFF (1024 + 2 * 9216)          // 19456
#define G2_SMEM (B2_OFF + 2 * 17408)      // 54272

// ======================= GEMM1 =======================
// hidden[slot, n] = silu(xh@W1)[n] * (xh@W2)[n]. CTA 128m x 64n dual. KC=64, 16 chunks.
__global__ void __launch_bounds__(256, 2) gemm1_kernel(const float* __restrict__ w12) {
    int e = blockIdx.z;
    int cnt = g_cnt[e];
    int m0 = blockIdx.x * 128;
    if (m0 >= cnt) return;
    int n0 = blockIdx.y * 64;

    extern __shared__ char smem[];
    uint32_t sb = smem_u32(smem);
    int* slot = (int*)smem;
    int* tok  = (int*)(smem + 512);
    int tid = threadIdx.x, wid = tid >> 5, lane = tid & 31;
    int g = lane >> 2, tg = lane & 3;
    int wm = (wid & 3) * 32, wn = (wid >> 2) * 32;
    int q = lane >> 3, r = lane & 7;

    if (tid < 128) {
        int m = m0 + tid;
        int s = g_list[e][(m < cnt) ? m : 0];
        slot[tid] = (m < cnt) ? s : -1;
        tok[tid]  = s >> 1;
    }
    __syncthreads();

    const float* wb0 = w12 + (size_t)e * D * TWOH;
    uint32_t aBase = sb + A_OFF + (uint32_t)((wm + (q & 1) * 8 + r) * 144 + (q >> 1) * 16);
    uint32_t bBase = sb + B_OFF + (uint32_t)(((q & 1) * 8 + r) * 272 + (q >> 1) * 16);

    float4 rbv[8];

    // ---- prologue: A(0) cp.async, B(0) reg-stage ----
#pragma unroll
    for (int j = 0; j < 4; j++) {
        int c = tid + j * 256;
        int m = c >> 3, kq = c & 7;
        CP_ASYNC16(sb + A_OFF + m * 144 + kq * 16, g_xh + (size_t)tok[m] * D + kq * 8);
    }
    CP_COMMIT();
#pragma unroll
    for (int j = 0; j < 8; j++) {
        int c = tid + j * 256;
        int k = c >> 5, n4 = c & 31;
        int col = (n4 < 16) ? (n0 + n4 * 4) : (Hh + n0 + (n4 - 16) * 4);
        rbv[j] = *(const float4*)(wb0 + (size_t)k * TWOH + col);
    }
#pragma unroll
    for (int j = 0; j < 8; j++) {
        int c = tid + j * 256;
        int k = c >> 5, n4 = c & 31;
        uint2 u;
        u.x = h2u(__floats2half2_rn(rbv[j].x, rbv[j].y));
        u.y = h2u(__floats2half2_rn(rbv[j].z, rbv[j].w));
        *(uint2*)(smem + B_OFF + k * 272 + n4 * 8) = u;
    }
    CP_WAIT0();
    __syncthreads();

    float acc1[2][4][4] = {}, acc2[2][4][4] = {};

    for (int i = 0; i < 16; i++) {
        int cur = i & 1, nxt = cur ^ 1;
        if (i + 1 < 16) {
            int k0 = (i + 1) * 64;
#pragma unroll
            for (int j = 0; j < 4; j++) {
                int c = tid + j * 256;
                int m = c >> 3, kq = c & 7;
                CP_ASYNC16(sb + A_OFF + nxt * A_STG + m * 144 + kq * 16,
                           g_xh + (size_t)tok[m] * D + k0 + kq * 8);
            }
            CP_COMMIT();
#pragma unroll
            for (int j = 0; j < 8; j++) {
                int c = tid + j * 256;
                int k = c >> 5, n4 = c & 31;
                int col = (n4 < 16) ? (n0 + n4 * 4) : (Hh + n0 + (n4 - 16) * 4);
                rbv[j] = *(const float4*)(wb0 + (size_t)(k0 + k) * TWOH + col);
            }
        }
        // compute on cur
        {
            uint32_t aA = aBase + cur * A_STG;
            uint32_t bA = bBase + cur * B_STG;
#pragma unroll
            for (int kt = 0; kt < 4; kt++) {
                uint32_t a[2][4];
                ldsm4(a[0], aA + kt * 32);
                ldsm4(a[1], aA + kt * 32 + 16 * 144);
                uint32_t b1[8], b2[8];
                uint32_t bk = bA + kt * (16 * 272);
                ldsm4t(b1 + 0, bk + (wn + 0) * 2);
                ldsm4t(b1 + 4, bk + (wn + 16) * 2);
                ldsm4t(b2 + 0, bk + (64 + wn) * 2);
                ldsm4t(b2 + 4, bk + (64 + wn + 16) * 2);
#pragma unroll
                for (int nt = 0; nt < 4; nt++) {
#pragma unroll
                    for (int mt = 0; mt < 2; mt++) {
                        mma16(acc1[mt][nt], a[mt], b1[2 * nt], b1[2 * nt + 1]);
                        mma16(acc2[mt][nt], a[mt], b2[2 * nt], b2[2 * nt + 1]);
                    }
                }
            }
        }
        if (i + 1 < 16) {
#pragma unroll
            for (int j = 0; j < 8; j++) {
                int c = tid + j * 256;
                int k = c >> 5, n4 = c & 31;
                uint2 u;
                u.x = h2u(__floats2half2_rn(rbv[j].x, rbv[j].y));
                u.y = h2u(__floats2half2_rn(rbv[j].z, rbv[j].w));
                *(uint2*)(smem + B_OFF + nxt * B_STG + k * 272 + n4 * 8) = u;
            }
        }
        CP_WAIT0();
        __syncthreads();
    }

    // epilogue: swiglu fuse, store fp16 hidden
#pragma unroll
    for (int mt = 0; mt < 2; mt++) {
        int r0 = wm + mt * 16 + g;
        int s0 = slot[r0], s1 = slot[r0 + 8];
#pragma unroll
        for (int nt = 0; nt < 4; nt++) {
            int col = n0 + wn + nt * 8 + tg * 2;
            if (s0 >= 0) {
                float h1a = acc1[mt][nt][0], h2a = acc2[mt][nt][0];
                float h1b = acc1[mt][nt][1], h2b = acc2[mt][nt][1];
                float oa = h2a * h1a / (1.0f + expf(-h1a));
                float ob = h2b * h1b / (1.0f + expf(-h1b));
                *(uint32_t*)(g_hiddenh + (size_t)s0 * Hh + col) = h2u(__floats2half2_rn(oa, ob));
            }
            if (s1 >= 0) {
                float h1a = acc1[mt][nt][2], h2a = acc2[mt][nt][2];
                float h1b = acc1[mt][nt][3], h2b = acc2[mt][nt][3];
                float oa = h2a * h1a / (1.0f + expf(-h1a));
                float ob = h2b * h1b / (1.0f + expf(-h1b));
                *(uint32_t*)(g_hiddenh + (size_t)s1 * Hh + col) = h2u(__floats2half2_rn(oa, ob));
            }
        }
    }
}

// ======================= GEMM2 (M-tile 64) =======================
// out[tok, n] += wt[slot] * (hiddenh @ w3)[n] via atomics. CTA 64m x 128n. KC=64, 32 chunks.
// 8 warps: warp tile 16m x 64n. acc[8][4] = 32 regs.
__global__ void __launch_bounds__(256, 2) gemm2_kernel(const float* __restrict__ w3,
                                                       float* __restrict__ out, int out_size) {
    if (blockIdx.x == 0 && blockIdx.y == 0 && blockIdx.z == 0 && threadIdx.x == 0
        && out_size > T * D)
        out[T * D] = 0.01f * g_aux / (float)(T * E);

    int e = blockIdx.z;
    int cnt = g_cnt[e];
    int m0 = blockIdx.x * 64;
    if (m0 >= cnt) return;
    int n0 = blockIdx.y * 128;

    extern __shared__ char smem[];
    uint32_t sb = smem_u32(smem);
    int* slot = (int*)smem;
    int* srcs = (int*)(smem + 512);
    int tid = threadIdx.x, wid = tid >> 5, lane = tid & 31;
    int g = lane >> 2, tg = lane & 3;
    int wm = (wid & 3) * 16, wn = (wid >> 2) * 64;
    int q = lane >> 3, r = lane & 7;

    if (tid < 64) {
        int m = m0 + tid;
        int s = g_list[e][(m < cnt) ? m : 0];
        slot[tid] = (m < cnt) ? s : -1;
        srcs[tid] = s;
    }
    __syncthreads();

    const float* wb0 = w3 + (size_t)e * Hh * D + n0;
    uint32_t aBase = sb + A_OFF + (uint32_t)((wm + (q & 1) * 8 + r) * 144 + (q >> 1) * 16);
    uint32_t bBase = sb + B2_OFF + (uint32_t)(((q & 1) * 8 + r) * 272 + (q >> 1) * 16);

    float4 rbv[8];

    // ---- prologue: A(0) cp.async (64 rows x 8 segs = 512 -> 2 iters), B(0) reg-stage ----
#pragma unroll
    for (int j = 0; j < 2; j++) {
        int c = tid + j * 256;
        int m = c >> 3, kq = c & 7;
        CP_ASYNC16(sb + A_OFF + m * 144 + kq * 16, g_hiddenh + (size_t)srcs[m] * Hh + kq * 8);
    }
    CP_COMMIT();
#pragma unroll
    for (int j = 0; j < 8; j++) {
        int c = tid + j * 256;
        int k = c >> 5, n4 = c & 31;
        rbv[j] = *(const float4*)(wb0 + (size_t)k * D + n4 * 4);
    }
#pragma unroll
    for (int j = 0; j < 8; j++) {
        int c = tid + j * 256;
        int k = c >> 5, n4 = c & 31;
        uint2 u;
        u.x = h2u(__floats2half2_rn(rbv[j].x, rbv[j].y));
        u.y = h2u(__floats2half2_rn(rbv[j].z, rbv[j].w));
        *(uint2*)(smem + B2_OFF + k * 272 + n4 * 8) = u;
    }
    CP_WAIT0();
    __syncthreads();

    float acc[8][4] = {};

    for (int i = 0; i < 32; i++) {
        int cur = i & 1, nxt = cur ^ 1;
        if (i + 1 < 32) {
            int k0 = (i + 1) * 64;
#pragma unroll
            for (int j = 0; j < 2; j++) {
                int c = tid + j * 256;
                int m = c >> 3, kq = c & 7;
                CP_ASYNC16(sb + A_OFF + nxt * A2_STG + m * 144 + kq * 16,
                           g_hiddenh + (size_t)srcs[m] * Hh + k0 + kq * 8);
            }
            CP_COMMIT();
#pragma unroll
            for (int j = 0; j < 8; j++) {
                int c = tid + j * 256;
                int k = c >> 5, n4 = c & 31;
                rbv[j] = *(const float4*)(wb0 + (size_t)(k0 + k) * D + n4 * 4);
            }
        }
        {
            uint32_t aA = aBase + cur * A2_STG;
            uint32_t bA = bBase + cur * B_STG;
#pragma unroll
            for (int kt = 0; kt < 4; kt++) {
                uint32_t a[4];
                ldsm4(a, aA + kt * 32);
                uint32_t b[16];
                uint32_t bk = bA + kt * (16 * 272);
                ldsm4t(b + 0,  bk + (wn + 0) * 2);
                ldsm4t(b + 4,  bk + (wn + 16) * 2);
                ldsm4t(b + 8,  bk + (wn + 32) * 2);
                ldsm4t(b + 12, bk + (wn + 48) * 2);
#pragma unroll
                for (int nt = 0; nt < 8; nt++)
                    mma16(acc[nt], a, b[2 * nt], b[2 * nt + 1]);
            }
        }
        if (i + 1 < 32) {
#pragma unroll
            for (int j = 0; j < 8; j++) {
                int c = tid + j * 256;
                int k = c >> 5, n4 = c & 31;
                uint2 u;
                u.x = h2u(__floats2half2_rn(rbv[j].x, rbv[j].y));
                u.y = h2u(__floats2half2_rn(rbv[j].z, rbv[j].w));
                *(uint2*)(smem + B2_OFF + nxt * B_STG + k * 272 + n4 * 8) = u;
            }
        }
        CP_WAIT0();
        __syncthreads();
    }

    // epilogue: weighted atomic accumulate (2 commutative fp32 adds per element)
    {
        int r0 = wm + g;
        int s0 = slot[r0], s1 = slot[r0 + 8];
        float w0 = (s0 >= 0) ? g_wt[s0] : 0.0f;
        float w1 = (s1 >= 0) ? g_wt[s1] : 0.0f;
        float* o0 = (s0 >= 0) ? (out + (size_t)(s0 >> 1) * D) : 0;
        float* o1 = (s1 >= 0) ? (out + (size_t)(s1 >> 1) * D) : 0;
#pragma unroll
        for (int nt = 0; nt < 8; nt++) {
            int col = n0 + wn + nt * 8 + tg * 2;
            if (s0 >= 0) {
                atomicAdd(o0 + col,     w0 * acc[nt][0]);
                atomicAdd(o0 + col + 1, w0 * acc[nt][1]);
            }
            if (s1 >= 0) {
                atomicAdd(o1 + col,     w1 * acc[nt][2]);
                atomicAdd(o1 + col + 1, w1 * acc[nt][3]);
            }
        }
    }
}

// ======================= launch =======================
extern "C" void kernel_launch(void* const* d_in, const int* in_sizes, int n_in,
                              void* d_out, int out_size) {
    const float* x   = (const float*)d_in[0];
    const float* rw  = (const float*)d_in[1];
    const float* rb  = (const float*)d_in[2];
    const float* w12 = (const float*)d_in[3];
    const float* w3  = (const float*)d_in[4];
    float* out = (float*)d_out;

    cudaFuncSetAttribute(gemm1_kernel, cudaFuncAttributeMaxDynamicSharedMemorySize, G1_SMEM);
    cudaFuncSetAttribute(gemm2_kernel, cudaFuncAttributeMaxDynamicSharedMemorySize, G2_SMEM);

    zero_kernel<<<1, 32>>>();                                          // 0
    router_kernel<<<T / 8, 256>>>(x, rw, rb, out);                     // 1 (x->fp16 + out zero)
    gemm1_kernel<<<dim3(16, 32, E), 256, G1_SMEM>>>(w12);              // 2
    gemm2_kernel<<<dim3(32, 8, E), 256, G2_SMEM>>>(w3, out, out_size); // 3 (ncu slot)
}

// round 16
// speedup vs baseline: 1.1028x; 1.1028x over previous
#include <cuda_runtime.h>
#include <cuda_fp16.h>
#include <cstdint>
#include <math.h>

#define T 2048        // B*S tokens
#define D 1024
#define Hh 2048
#define E 8
#define TWOH 4096
#define NSLOT (T * 2)

// ---- scratch ----
__device__ int    g_cnt[E];
__device__ int    g_list[E][T];
__device__ float  g_wt[NSLOT];
__device__ __half g_xh[(size_t)T * D];            // fp16 x (4 MB)
__device__ __half g_hiddenh[(size_t)NSLOT * Hh];  // fp16 hidden (16 MB)
__device__ float  g_aux;

// ======================= helpers =======================
__device__ __forceinline__ uint32_t smem_u32(const void* p) {
    uint32_t a;
    asm("{ .reg .u64 t; cvta.to.shared.u64 t, %1; cvt.u32.u64 %0, t; }" : "=r"(a) : "l"(p));
    return a;
}
__device__ __forceinline__ uint32_t h2u(__half2 h) { return *(uint32_t*)&h; }

#define CP_ASYNC16(dst, src) \
    asm volatile("cp.async.cg.shared.global [%0], [%1], 16;" :: "r"(dst), "l"(src))
#define CP_COMMIT() asm volatile("cp.async.commit_group;")
#define CP_WAIT0()  asm volatile("cp.async.wait_group 0;" ::: "memory")

__device__ __forceinline__ void ldsm4(uint32_t* r, uint32_t addr) {
    asm volatile("ldmatrix.sync.aligned.m8n8.x4.shared.b16 {%0,%1,%2,%3},[%4];"
        : "=r"(r[0]), "=r"(r[1]), "=r"(r[2]), "=r"(r[3]) : "r"(addr));
}
__device__ __forceinline__ void ldsm4t(uint32_t* r, uint32_t addr) {
    asm volatile("ldmatrix.sync.aligned.m8n8.x4.trans.shared.b16 {%0,%1,%2,%3},[%4];"
        : "=r"(r[0]), "=r"(r[1]), "=r"(r[2]), "=r"(r[3]) : "r"(addr));
}
__device__ __forceinline__ void mma16(float* c, const uint32_t* a, uint32_t b0, uint32_t b1) {
    asm volatile(
        "mma.sync.aligned.m16n8k16.row.col.f32.f16.f16.f32 "
        "{%0,%1,%2,%3},{%4,%5,%6,%7},{%8,%9},{%0,%1,%2,%3};"
        : "+f"(c[0]), "+f"(c[1]), "+f"(c[2]), "+f"(c[3])
        : "r"(a[0]), "r"(a[1]), "r"(a[2]), "r"(a[3]), "r"(b0), "r"(b1));
}

// ======================= small kernels =======================
// tiny init: expert counters + aux
__global__ void zero_kernel() {
    int i = threadIdx.x;
    if (i < E) g_cnt[i] = 0;
    if (i == 0) g_aux = 0.0f;
}

// router + x->fp16 conversion + out-row zeroing, fused (one warp per token)
__global__ void router_kernel(const float* __restrict__ x,
                              const float* __restrict__ rw,
                              const float* __restrict__ rb,
                              float* __restrict__ out) {
    int warp = threadIdx.x >> 5;
    int lane = threadIdx.x & 31;
    int t = blockIdx.x * (blockDim.x >> 5) + warp;
    if (t >= T) return;

    // zero this token's output row (atomic accumulation target)
    {
        float4* orow = (float4*)(out + (size_t)t * D);
#pragma unroll
        for (int j = 0; j < 8; j++)
            orow[lane + j * 32] = make_float4(0.f, 0.f, 0.f, 0.f);
    }

    const float2* xr = (const float2*)(x + (size_t)t * D);
    uint32_t* xo = (uint32_t*)(g_xh + (size_t)t * D);
    float acc[E];
#pragma unroll
    for (int e = 0; e < E; e++) acc[e] = 0.0f;
#pragma unroll 4
    for (int p = lane; p < D / 2; p += 32) {
        float2 v = xr[p];
        xo[p] = h2u(__floats2half2_rn(v.x, v.y));
#pragma unroll
        for (int e = 0; e < E; e++)
            acc[e] += v.x * rw[e * D + 2 * p] + v.y * rw[e * D + 2 * p + 1];
    }
#pragma unroll
    for (int e = 0; e < E; e++) {
#pragma unroll
        for (int off = 16; off; off >>= 1)
            acc[e] += __shfl_xor_sync(0xffffffffu, acc[e], off);
    }
    if (lane == 0) {
        float score[E];
        float auxl = 0.0f;
#pragma unroll
        for (int e = 0; e < E; e++) {
            float lg = acc[e] + rb[e];
            auxl += lg * lg;
            score[e] = 1.0f / (1.0f + expf(-lg));
        }
        int e0 = 0;
#pragma unroll
        for (int e = 1; e < E; e++) if (score[e] > score[e0]) e0 = e;
        int e1 = -1;
#pragma unroll
        for (int e = 0; e < E; e++) {
            if (e == e0) continue;
            if (e1 < 0 || score[e] > score[e1]) e1 = e;
        }
        float s0 = score[e0], s1 = score[e1];
        float inv = 1.0f / (s0 + s1 + 1e-6f);
        g_wt[2 * t]     = s0 * inv;
        g_wt[2 * t + 1] = s1 * inv;
        int p0 = atomicAdd(&g_cnt[e0], 1); g_list[e0][p0] = 2 * t;
        int p1 = atomicAdd(&g_cnt[e1], 1); g_list[e1][p1] = 2 * t + 1;
        atomicAdd(&g_aux, auxl);
    }
}

// ======================= GEMM common layout =======================
// slot[128]@0, tok/src[128]@512
// A: [m:128][k:64] fp16, row stride 144B. stage = 18432B x2
// B: [k:64][n:128+8pad] fp16, row stride 272B. stage = 17408B x2
#define A_OFF 1024
#define A_STG 18432
#define B_OFF (1024 + 2 * 18432)
#define B_STG 17408
#define G_SMEM (B_OFF + 2 * 17408)

// ======================= GEMM1 =======================
// hidden[slot, n] = silu(xh@W1)[n] * (xh@W2)[n]. CTA 128m x 64n dual. KC=64, 16 chunks.
__global__ void __launch_bounds__(256, 2) gemm1_kernel(const float* __restrict__ w12) {
    int e = blockIdx.z;
    int cnt = g_cnt[e];
    int m0 = blockIdx.x * 128;
    if (m0 >= cnt) return;
    int n0 = blockIdx.y * 64;

    extern __shared__ char smem[];
    uint32_t sb = smem_u32(smem);
    int* slot = (int*)smem;
    int* tok  = (int*)(smem + 512);
    int tid = threadIdx.x, wid = tid >> 5, lane = tid & 31;
    int g = lane >> 2, tg = lane & 3;
    int wm = (wid & 3) * 32, wn = (wid >> 2) * 32;
    int q = lane >> 3, r = lane & 7;

    if (tid < 128) {
        int m = m0 + tid;
        int s = g_list[e][(m < cnt) ? m : 0];
        slot[tid] = (m < cnt) ? s : -1;
        tok[tid]  = s >> 1;
    }
    __syncthreads();

    const float* wb0 = w12 + (size_t)e * D * TWOH;
    uint32_t aBase = sb + A_OFF + (uint32_t)((wm + (q & 1) * 8 + r) * 144 + (q >> 1) * 16);
    uint32_t bBase = sb + B_OFF + (uint32_t)(((q & 1) * 8 + r) * 272 + (q >> 1) * 16);

    float4 rbv[8];

    // ---- prologue: A(0) cp.async, B(0) reg-stage ----
#pragma unroll
    for (int j = 0; j < 4; j++) {
        int c = tid + j * 256;
        int m = c >> 3, kq = c & 7;
        CP_ASYNC16(sb + A_OFF + m * 144 + kq * 16, g_xh + (size_t)tok[m] * D + kq * 8);
    }
    CP_COMMIT();
#pragma unroll
    for (int j = 0; j < 8; j++) {
        int c = tid + j * 256;
        int k = c >> 5, n4 = c & 31;
        int col = (n4 < 16) ? (n0 + n4 * 4) : (Hh + n0 + (n4 - 16) * 4);
        rbv[j] = *(const float4*)(wb0 + (size_t)k * TWOH + col);
    }
#pragma unroll
    for (int j = 0; j < 8; j++) {
        int c = tid + j * 256;
        int k = c >> 5, n4 = c & 31;
        uint2 u;
        u.x = h2u(__floats2half2_rn(rbv[j].x, rbv[j].y));
        u.y = h2u(__floats2half2_rn(rbv[j].z, rbv[j].w));
        *(uint2*)(smem + B_OFF + k * 272 + n4 * 8) = u;
    }
    CP_WAIT0();
    __syncthreads();

    float acc1[2][4][4] = {}, acc2[2][4][4] = {};

    for (int i = 0; i < 16; i++) {
        int cur = i & 1, nxt = cur ^ 1;
        if (i + 1 < 16) {
            int k0 = (i + 1) * 64;
#pragma unroll
            for (int j = 0; j < 4; j++) {
                int c = tid + j * 256;
                int m = c >> 3, kq = c & 7;
                CP_ASYNC16(sb + A_OFF + nxt * A_STG + m * 144 + kq * 16,
                           g_xh + (size_t)tok[m] * D + k0 + kq * 8);
            }
            CP_COMMIT();
#pragma unroll
            for (int j = 0; j < 8; j++) {
                int c = tid + j * 256;
                int k = c >> 5, n4 = c & 31;
                int col = (n4 < 16) ? (n0 + n4 * 4) : (Hh + n0 + (n4 - 16) * 4);
                rbv[j] = *(const float4*)(wb0 + (size_t)(k0 + k) * TWOH + col);
            }
        }
        // compute on cur
        {
            uint32_t aA = aBase + cur * A_STG;
            uint32_t bA = bBase + cur * B_STG;
#pragma unroll
            for (int kt = 0; kt < 4; kt++) {
                uint32_t a[2][4];
                ldsm4(a[0], aA + kt * 32);
                ldsm4(a[1], aA + kt * 32 + 16 * 144);
                uint32_t b1[8], b2[8];
                uint32_t bk = bA + kt * (16 * 272);
                ldsm4t(b1 + 0, bk + (wn + 0) * 2);
                ldsm4t(b1 + 4, bk + (wn + 16) * 2);
                ldsm4t(b2 + 0, bk + (64 + wn) * 2);
                ldsm4t(b2 + 4, bk + (64 + wn + 16) * 2);
#pragma unroll
                for (int nt = 0; nt < 4; nt++) {
#pragma unroll
                    for (int mt = 0; mt < 2; mt++) {
                        mma16(acc1[mt][nt], a[mt], b1[2 * nt], b1[2 * nt + 1]);
                        mma16(acc2[mt][nt], a[mt], b2[2 * nt], b2[2 * nt + 1]);
                    }
                }
            }
        }
        if (i + 1 < 16) {
#pragma unroll
            for (int j = 0; j < 8; j++) {
                int c = tid + j * 256;
                int k = c >> 5, n4 = c & 31;
                uint2 u;
                u.x = h2u(__floats2half2_rn(rbv[j].x, rbv[j].y));
                u.y = h2u(__floats2half2_rn(rbv[j].z, rbv[j].w));
                *(uint2*)(smem + B_OFF + nxt * B_STG + k * 272 + n4 * 8) = u;
            }
        }
        CP_WAIT0();
        __syncthreads();
    }

    // epilogue: swiglu fuse, store fp16 hidden
#pragma unroll
    for (int mt = 0; mt < 2; mt++) {
        int r0 = wm + mt * 16 + g;
        int s0 = slot[r0], s1 = slot[r0 + 8];
#pragma unroll
        for (int nt = 0; nt < 4; nt++) {
            int col = n0 + wn + nt * 8 + tg * 2;
            if (s0 >= 0) {
                float h1a = acc1[mt][nt][0], h2a = acc2[mt][nt][0];
                float h1b = acc1[mt][nt][1], h2b = acc2[mt][nt][1];
                float oa = h2a * h1a / (1.0f + expf(-h1a));
                float ob = h2b * h1b / (1.0f + expf(-h1b));
                *(uint32_t*)(g_hiddenh + (size_t)s0 * Hh + col) = h2u(__floats2half2_rn(oa, ob));
            }
            if (s1 >= 0) {
                float h1a = acc1[mt][nt][2], h2a = acc2[mt][nt][2];
                float h1b = acc1[mt][nt][3], h2b = acc2[mt][nt][3];
                float oa = h2a * h1a / (1.0f + expf(-h1a));
                float ob = h2b * h1b / (1.0f + expf(-h1b));
                *(uint32_t*)(g_hiddenh + (size_t)s1 * Hh + col) = h2u(__floats2half2_rn(oa, ob));
            }
        }
    }
}

// ======================= GEMM2 =======================
// out[tok, n] += wt[slot] * (hiddenh @ w3)[n] via atomics. CTA 128m x 128n. KC=64, 32 chunks.
__global__ void __launch_bounds__(256, 2) gemm2_kernel(const float* __restrict__ w3,
                                                       float* __restrict__ out, int out_size) {
    // aux-loss write (exactly once, before any early return)
    if (blockIdx.x == 0 && blockIdx.y == 0 && blockIdx.z == 0 && threadIdx.x == 0
        && out_size > T * D)
        out[T * D] = 0.01f * g_aux / (float)(T * E);

    int e = blockIdx.z;
    int cnt = g_cnt[e];
    int m0 = blockIdx.x * 128;
    if (m0 >= cnt) return;
    int n0 = blockIdx.y * 128;

    extern __shared__ char smem[];
    uint32_t sb = smem_u32(smem);
    int* slot = (int*)smem;
    int* srcs = (int*)(smem + 512);
    int tid = threadIdx.x, wid = tid >> 5, lane = tid & 31;
    int g = lane >> 2, tg = lane & 3;
    int wm = (wid & 3) * 32, wn = (wid >> 2) * 64;
    int q = lane >> 3, r = lane & 7;

    if (tid < 128) {
        int m = m0 + tid;
        int s = g_list[e][(m < cnt) ? m : 0];
        slot[tid] = (m < cnt) ? s : -1;
        srcs[tid] = s;
    }
    __syncthreads();

    const float* wb0 = w3 + (size_t)e * Hh * D + n0;
    uint32_t aBase = sb + A_OFF + (uint32_t)((wm + (q & 1) * 8 + r) * 144 + (q >> 1) * 16);
    uint32_t bBase = sb + B_OFF + (uint32_t)(((q & 1) * 8 + r) * 272 + (q >> 1) * 16);

    float4 rbv[8];

#pragma unroll
    for (int j = 0; j < 4; j++) {
        int c = tid + j * 256;
        int m = c >> 3, kq = c & 7;
        CP_ASYNC16(sb + A_OFF + m * 144 + kq * 16, g_hiddenh + (size_t)srcs[m] * Hh + kq * 8);
    }
    CP_COMMIT();
#pragma unroll
    for (int j = 0; j < 8; j++) {
        int c = tid + j * 256;
        int k = c >> 5, n4 = c & 31;
        rbv[j] = *(const float4*)(wb0 + (size_t)k * D + n4 * 4);
    }
#pragma unroll
    for (int j = 0; j < 8; j++) {
        int c = tid + j * 256;
        int k = c >> 5, n4 = c & 31;
        uint2 u;
        u.x = h2u(__floats2half2_rn(rbv[j].x, rbv[j].y));
        u.y = h2u(__floats2half2_rn(rbv[j].z, rbv[j].w));
        *(uint2*)(smem + B_OFF + k * 272 + n4 * 8) = u;
    }
    CP_WAIT0();
    __syncthreads();

    float acc[2][8][4] = {};

    for (int i = 0; i < 32; i++) {
        int cur = i & 1, nxt = cur ^ 1;
        if (i + 1 < 32) {
            int k0 = (i + 1) * 64;
#pragma unroll
            for (int j = 0; j < 4; j++) {
                int c = tid + j * 256;
                int m = c >> 3, kq = c & 7;
                CP_ASYNC16(sb + A_OFF + nxt * A_STG + m * 144 + kq * 16,
                           g_hiddenh + (size_t)srcs[m] * Hh + k0 + kq * 8);
            }
            CP_COMMIT();
#pragma unroll
            for (int j = 0; j < 8; j++) {
                int c = tid + j * 256;
                int k = c >> 5, n4 = c & 31;
                rbv[j] = *(const float4*)(wb0 + (size_t)(k0 + k) * D + n4 * 4);
            }
        }
        {
            uint32_t aA = aBase + cur * A_STG;
            uint32_t bA = bBase + cur * B_STG;
#pragma unroll
            for (int kt = 0; kt < 4; kt++) {
                uint32_t a[2][4];
                ldsm4(a[0], aA + kt * 32);
                ldsm4(a[1], aA + kt * 32 + 16 * 144);
                uint32_t b[16];
                uint32_t bk = bA + kt * (16 * 272);
                ldsm4t(b + 0,  bk + (wn + 0) * 2);
                ldsm4t(b + 4,  bk + (wn + 16) * 2);
                ldsm4t(b + 8,  bk + (wn + 32) * 2);
                ldsm4t(b + 12, bk + (wn + 48) * 2);
#pragma unroll
                for (int nt = 0; nt < 8; nt++) {
#pragma unroll
                    for (int mt = 0; mt < 2; mt++)
                        mma16(acc[mt][nt], a[mt], b[2 * nt], b[2 * nt + 1]);
                }
            }
        }
        if (i + 1 < 32) {
#pragma unroll
            for (int j = 0; j < 8; j++) {
                int c = tid + j * 256;
                int k = c >> 5, n4 = c & 31;
                uint2 u;
                u.x = h2u(__floats2half2_rn(rbv[j].x, rbv[j].y));
                u.y = h2u(__floats2half2_rn(rbv[j].z, rbv[j].w));
                *(uint2*)(smem + B_OFF + nxt * B_STG + k * 272 + n4 * 8) = u;
            }
        }
        CP_WAIT0();
        __syncthreads();
    }

    // epilogue: weighted atomic accumulate into out (2 contributions/element total)
#pragma unroll
    for (int mt = 0; mt < 2; mt++) {
        int r0 = wm + mt * 16 + g;
        int s0 = slot[r0], s1 = slot[r0 + 8];
        float w0 = (s0 >= 0) ? g_wt[s0] : 0.0f;
        float w1 = (s1 >= 0) ? g_wt[s1] : 0.0f;
        float* o0 = (s0 >= 0) ? (out + (size_t)(s0 >> 1) * D) : 0;
        float* o1 = (s1 >= 0) ? (out + (size_t)(s1 >> 1) * D) : 0;
#pragma unroll
        for (int nt = 0; nt < 8; nt++) {
            int col = n0 + wn + nt * 8 + tg * 2;
            if (s0 >= 0) {
                atomicAdd(o0 + col,     w0 * acc[mt][nt][0]);
                atomicAdd(o0 + col + 1, w0 * acc[mt][nt][1]);
            }
            if (s1 >= 0) {
                atomicAdd(o1 + col,     w1 * acc[mt][nt][2]);
                atomicAdd(o1 + col + 1, w1 * acc[mt][nt][3]);
            }
        }
    }
}

// ======================= launch =======================
extern "C" void kernel_launch(void* const* d_in, const int* in_sizes, int n_in,
                              void* d_out, int out_size) {
    const float* x   = (const float*)d_in[0];
    const float* rw  = (const float*)d_in[1];
    const float* rb  = (const float*)d_in[2];
    const float* w12 = (const float*)d_in[3];
    const float* w3  = (const float*)d_in[4];
    float* out = (float*)d_out;

    cudaFuncSetAttribute(gemm1_kernel, cudaFuncAttributeMaxDynamicSharedMemorySize, G_SMEM);
    cudaFuncSetAttribute(gemm2_kernel, cudaFuncAttributeMaxDynamicSharedMemorySize, G_SMEM);

    zero_kernel<<<1, 32>>>();                                          // 0 (tiny)
    router_kernel<<<T / 8, 256>>>(x, rw, rb, out);                     // 1 (x->fp16 + out zero)
    gemm1_kernel<<<dim3(16, 32, E), 256, G_SMEM>>>(w12);               // 2
    gemm2_kernel<<<dim3(16, 8, E), 256, G_SMEM>>>(w3, out, out_size);  // 3 (ncu slot)
}